// round 9
// baseline (speedup 1.0000x reference)
#include <cuda_runtime.h>
#include <cuda_fp8.h>
#include <cstdint>

// ============================================================
// FP8Linear: out = (fp8(x*sx)/sx) @ (fp8(w*sw)/sw) + bias
// Computed as fp8 mma.sync GEMM * (ax/448)*(aw/448) + bias.
// (tcgen05 unavailable: harness compiles via compute_103 virtual target.)
// Shapes: x [8192,4096], w [4096,4096], bias [4096], out [8192,4096]
// GEMM: 128x256 CTA tile, warp tile 64x64, 3-stage cp.async, 1 sync/iter.
// ============================================================

#define M_MAX   8192
#define K_MAX   4096
#define OUT_MAX 4096

__device__ unsigned int g_amax_bits[2];                                // [0]=x, [1]=w
__device__ __align__(16) unsigned char g_xq[(size_t)M_MAX * K_MAX];    // fp8 x, [M,K]
__device__ __align__(16) unsigned char g_wq[(size_t)OUT_MAX * K_MAX];  // fp8 w^T, [OUT,K]

// ---------------- helpers ----------------
__device__ __forceinline__ uint32_t smem_u32(const void* p) {
    uint32_t a;
    asm("{ .reg .u64 t; cvta.to.shared.u64 t, %1; cvt.u32.u64 %0, t; }" : "=r"(a) : "l"(p));
    return a;
}
__device__ __forceinline__ uint32_t sw128(uint32_t off) { return off ^ ((off >> 3) & 0x70); }

__device__ __forceinline__ void cp16(uint32_t saddr, const void* gptr) {
    asm volatile("cp.async.cg.shared.global [%0], [%1], 16;"
                 :: "r"(saddr), "l"(gptr) : "memory");
}
#define CP_COMMIT() asm volatile("cp.async.commit_group;" ::: "memory")
#define CP_WAIT1()  asm volatile("cp.async.wait_group 1;" ::: "memory")

__device__ __forceinline__ void ldm_x4(uint32_t addr, uint32_t& r0, uint32_t& r1,
                                       uint32_t& r2, uint32_t& r3) {
    asm volatile("ldmatrix.sync.aligned.m8n8.x4.shared.b16 {%0,%1,%2,%3}, [%4];"
                 : "=r"(r0), "=r"(r1), "=r"(r2), "=r"(r3) : "r"(addr));
}

__device__ __forceinline__ void mma_fp8(float* d, const uint32_t* a, uint32_t b0, uint32_t b1) {
    asm volatile(
        "mma.sync.aligned.m16n8k32.row.col.f32.e4m3.e4m3.f32 "
        "{%0,%1,%2,%3}, {%4,%5,%6,%7}, {%8,%9}, {%0,%1,%2,%3};"
        : "+f"(d[0]), "+f"(d[1]), "+f"(d[2]), "+f"(d[3])
        : "r"(a[0]), "r"(a[1]), "r"(a[2]), "r"(a[3]), "r"(b0), "r"(b1));
}

// ---------------- prep kernels ----------------
__global__ void init_amax_kernel() {
    g_amax_bits[0] = 0u;
    g_amax_bits[1] = 0u;
}

__global__ void amax_kernel(const float4* __restrict__ p, int n4, int slot) {
    float m = 0.0f;
    for (int i = blockIdx.x * blockDim.x + threadIdx.x; i < n4; i += gridDim.x * blockDim.x) {
        float4 v = p[i];
        m = fmaxf(m, fmaxf(fmaxf(fabsf(v.x), fabsf(v.y)), fmaxf(fabsf(v.z), fabsf(v.w))));
    }
    #pragma unroll
    for (int o = 16; o > 0; o >>= 1) m = fmaxf(m, __shfl_xor_sync(0xFFFFFFFFu, m, o));
    __shared__ float wm[8];
    if ((threadIdx.x & 31) == 0) wm[threadIdx.x >> 5] = m;
    __syncthreads();
    if (threadIdx.x < 8) {
        m = wm[threadIdx.x];
        #pragma unroll
        for (int o = 4; o > 0; o >>= 1) m = fmaxf(m, __shfl_xor_sync(0xFFu, m, o));
        if (threadIdx.x == 0) atomicMax(&g_amax_bits[slot], __float_as_uint(m));
    }
}

__device__ __forceinline__ unsigned char f2fp8(float v) {
    return (unsigned char)__nv_cvt_float_to_fp8(v, __NV_SATFINITE, __NV_E4M3);
}

__global__ void quant_x_kernel(const float4* __restrict__ x, int n4) {
    float s = 448.0f / fmaxf(__uint_as_float(g_amax_bits[0]), 1e-12f);
    uint32_t* q = reinterpret_cast<uint32_t*>(g_xq);
    for (int i = blockIdx.x * blockDim.x + threadIdx.x; i < n4; i += gridDim.x * blockDim.x) {
        float4 v = x[i];
        uint32_t b0 = f2fp8(v.x * s), b1 = f2fp8(v.y * s), b2 = f2fp8(v.z * s), b3 = f2fp8(v.w * s);
        q[i] = b0 | (b1 << 8) | (b2 << 16) | (b3 << 24);
    }
}

// quantize + transpose weight: w [K, OUT] (row-major) -> g_wq [OUT, K]
__global__ void quant_w_t_kernel(const float* __restrict__ w, int K, int OUT) {
    __shared__ unsigned char t[32][33];
    int o0 = blockIdx.x * 32, k0 = blockIdx.y * 32;
    int tx = threadIdx.x, ty = threadIdx.y;  // (32, 8)
    float s = 448.0f / fmaxf(__uint_as_float(g_amax_bits[1]), 1e-12f);
    #pragma unroll
    for (int i = 0; i < 4; i++) {
        int k = k0 + ty + 8 * i, o = o0 + tx;
        t[ty + 8 * i][tx] = f2fp8(w[(size_t)k * OUT + o] * s);
    }
    __syncthreads();
    #pragma unroll
    for (int i = 0; i < 4; i++) {
        int o = o0 + ty + 8 * i, k = k0 + tx;
        g_wq[(size_t)o * K + k] = t[tx][ty + 8 * i];
    }
}

// ---------------- GEMM kernel ----------------
// CTA tile 128(M) x 256(N), K-chunk 128B fp8, 3-stage cp.async pipeline.
// 8 warps: 2(m) x 4(n); each warp computes 64x64 with m16n8k32 fp8 mma.
#define STAGES      3
#define A_BYTES     16384                     // 128 rows x 128B
#define B_BYTES     32768                     // 256 rows x 128B
#define STAGE_BYTES (A_BYTES + B_BYTES)       // 48 KB
#define GEMM_SMEM_TOTAL (STAGES * STAGE_BYTES)  // 144 KB

__global__ void __launch_bounds__(256, 1)
gemm_fp8_kernel(float* __restrict__ out, const float* __restrict__ bias,
                int K, int NOUT, int tiles_n)
{
    extern __shared__ char smem[];
    uint32_t smem_base = smem_u32(smem);
    int tid = threadIdx.x;
    int wid = tid >> 5, lid = tid & 31;
    int wm = wid & 1, wn = wid >> 1;           // warp grid: 2m x 4n

    // rasterization: group 8 M-tiles
    int bid = blockIdx.x;
    int group = 8 * tiles_n;
    int g = bid / group, r = bid % group;
    int tm = g * 8 + (r % 8);
    int tn = r / 8;

    const unsigned char* Abase = g_xq + (size_t)tm * 128 * K;
    const unsigned char* Bbase = g_wq + (size_t)tn * 256 * K;

    // per-thread load slots: A 4 x 16B, B 8 x 16B per stage
    uint32_t aswz[4], bswz[8];
    int arow[4], brow[8], acol[4], bcol[8];
    #pragma unroll
    for (int i = 0; i < 4; i++) {
        int j = tid + 256 * i;                  // 0..1023
        arow[i] = j >> 3; acol[i] = (j & 7) << 4;
        aswz[i] = sw128((uint32_t)(arow[i] * 128 + acol[i]));
    }
    #pragma unroll
    for (int i = 0; i < 8; i++) {
        int j = tid + 256 * i;                  // 0..2047
        brow[i] = j >> 3; bcol[i] = (j & 7) << 4;
        bswz[i] = sw128((uint32_t)(brow[i] * 128 + bcol[i]));
    }

    auto issue_load = [&](int kc, int stg) {
        const unsigned char* ga = Abase + (size_t)kc * 128;
        const unsigned char* gb = Bbase + (size_t)kc * 128;
        uint32_t sa = smem_base + stg * STAGE_BYTES;
        uint32_t sb = sa + A_BYTES;
        #pragma unroll
        for (int i = 0; i < 4; i++)
            cp16(sa + aswz[i], ga + (size_t)arow[i] * K + acol[i]);
        #pragma unroll
        for (int i = 0; i < 8; i++)
            cp16(sb + bswz[i], gb + (size_t)brow[i] * K + bcol[i]);
    };

    float acc[4][8][4];
    #pragma unroll
    for (int mf = 0; mf < 4; mf++)
        #pragma unroll
        for (int j = 0; j < 8; j++)
            #pragma unroll
            for (int k = 0; k < 4; k++) acc[mf][j][k] = 0.0f;

    // ldmatrix lane addressing: row = lid%16, byte-half = (lid/16)*16
    int lr = lid & 15, lh = (lid >> 4) << 4;

    const int kit = K / 128;
    issue_load(0, 0); CP_COMMIT();
    issue_load(1, 1); CP_COMMIT();

    for (int it = 0; it < kit; ++it) {
        CP_WAIT1();
        __syncthreads();        // all warps done reading stage (it-1)%3; stage it%3 ready
        if (it + 2 < kit) issue_load(it + 2, (it + 2) % STAGES);
        CP_COMMIT();

        int buf = it % STAGES;
        uint32_t sa = smem_base + buf * STAGE_BYTES;
        uint32_t sb = sa + A_BYTES;

        #pragma unroll
        for (int s = 0; s < 4; s++) {          // k32 steps within the 128B chunk
            uint32_t Ar[4][4];
            #pragma unroll
            for (int mf = 0; mf < 4; mf++) {
                uint32_t off = (uint32_t)((wm * 64 + mf * 16 + lr) * 128 + s * 32 + lh);
                ldm_x4(sa + sw128(off), Ar[mf][0], Ar[mf][1], Ar[mf][2], Ar[mf][3]);
            }
            uint32_t Br[4][4];
            #pragma unroll
            for (int nb = 0; nb < 4; nb++) {
                uint32_t off = (uint32_t)((wn * 64 + nb * 16 + lr) * 128 + s * 32 + lh);
                ldm_x4(sb + sw128(off), Br[nb][0], Br[nb][1], Br[nb][2], Br[nb][3]);
            }
            #pragma unroll
            for (int mf = 0; mf < 4; mf++)
                #pragma unroll
                for (int j = 0; j < 8; j++) {
                    uint32_t b0 = Br[j >> 1][(j & 1) ? 1 : 0];
                    uint32_t b1 = Br[j >> 1][(j & 1) ? 3 : 2];
                    mma_fp8(acc[mf][j], Ar[mf], b0, b1);
                }
        }
    }

    // epilogue: scale + bias, float2 stores
    float ax = fmaxf(__uint_as_float(g_amax_bits[0]), 1e-12f);
    float aw = fmaxf(__uint_as_float(g_amax_bits[1]), 1e-12f);
    float inv = (ax / 448.0f) * (aw / 448.0f);
    int row0 = tm * 128 + wm * 64 + (lid >> 2);
    int col0 = tn * 256 + wn * 64 + (lid & 3) * 2;
    #pragma unroll
    for (int mf = 0; mf < 4; mf++) {
        #pragma unroll
        for (int j = 0; j < 8; j++) {
            int rr = row0 + mf * 16;
            int cc = col0 + j * 8;
            float2 bv = *reinterpret_cast<const float2*>(bias + cc);
            float2 v0, v1;
            v0.x = acc[mf][j][0] * inv + bv.x;
            v0.y = acc[mf][j][1] * inv + bv.y;
            v1.x = acc[mf][j][2] * inv + bv.x;
            v1.y = acc[mf][j][3] * inv + bv.y;
            *reinterpret_cast<float2*>(out + (size_t)rr * NOUT + cc) = v0;
            *reinterpret_cast<float2*>(out + (size_t)(rr + 8) * NOUT + cc) = v1;
        }
    }
}

// ---------------- host launcher ----------------
extern "C" void kernel_launch(void* const* d_in, const int* in_sizes, int n_in,
                              void* d_out, int out_size) {
    const float* x    = (const float*)d_in[0];
    const float* w    = (const float*)d_in[1];
    const float* bias = (const float*)d_in[2];
    float* out        = (float*)d_out;

    int OUT = in_sizes[2];
    int IN  = in_sizes[1] / OUT;
    int M   = in_sizes[0] / IN;
    // shapes: M=8192, IN=K=4096, OUT=4096 (static buffers sized for these)

    cudaFuncSetAttribute(gemm_fp8_kernel,
                         cudaFuncAttributeMaxDynamicSharedMemorySize, GEMM_SMEM_TOTAL);

    init_amax_kernel<<<1, 1>>>();
    amax_kernel<<<1024, 256>>>((const float4*)x, in_sizes[0] / 4, 0);
    amax_kernel<<<1024, 256>>>((const float4*)w, in_sizes[1] / 4, 1);
    quant_x_kernel<<<2048, 256>>>((const float4*)x, in_sizes[0] / 4);
    {
        dim3 grid(OUT / 32, IN / 32), block(32, 8);
        quant_w_t_kernel<<<grid, block>>>(w, IN, OUT);
    }
    {
        int tiles_m = M / 128, tiles_n = OUT / 256;
        gemm_fp8_kernel<<<tiles_m * tiles_n, 256, GEMM_SMEM_TOTAL>>>(
            out, bias, IN, OUT, tiles_n);
    }
}

// round 12
// speedup vs baseline: 1.0336x; 1.0336x over previous
#include <cuda_runtime.h>
#include <cuda_fp8.h>
#include <cstdint>

// ============================================================
// FP8Linear: out = (fp8(x*sx)/sx) @ (fp8(w*sw)/sw) + bias
// Computed as fp8 mma.sync GEMM * (ax/448)*(aw/448) + bias.
// (tcgen05 unavailable: harness compiles via compute_103 virtual target.)
// Shapes: x [8192,4096], w [4096,4096], bias [4096], out [8192,4096]
// GEMM: 128x256 CTA tile, warp tile 64x64, 3-stage cp.async,
//       double-buffered ldmatrix fragments (LDSM hidden behind MMA).
// ============================================================

#define M_MAX   8192
#define K_MAX   4096
#define OUT_MAX 4096

__device__ unsigned int g_amax_bits[2];                                // [0]=x, [1]=w
__device__ __align__(16) unsigned char g_xq[(size_t)M_MAX * K_MAX];    // fp8 x, [M,K]
__device__ __align__(16) unsigned char g_wq[(size_t)OUT_MAX * K_MAX];  // fp8 w^T, [OUT,K]

// ---------------- helpers ----------------
__device__ __forceinline__ uint32_t smem_u32(const void* p) {
    uint32_t a;
    asm("{ .reg .u64 t; cvta.to.shared.u64 t, %1; cvt.u32.u64 %0, t; }" : "=r"(a) : "l"(p));
    return a;
}
__device__ __forceinline__ uint32_t sw128(uint32_t off) { return off ^ ((off >> 3) & 0x70); }

__device__ __forceinline__ void cp16(uint32_t saddr, const void* gptr) {
    asm volatile("cp.async.cg.shared.global [%0], [%1], 16;"
                 :: "r"(saddr), "l"(gptr) : "memory");
}
#define CP_COMMIT() asm volatile("cp.async.commit_group;" ::: "memory")
#define CP_WAIT1()  asm volatile("cp.async.wait_group 1;" ::: "memory")

__device__ __forceinline__ void ldm_x4(uint32_t addr, uint32_t& r0, uint32_t& r1,
                                       uint32_t& r2, uint32_t& r3) {
    asm volatile("ldmatrix.sync.aligned.m8n8.x4.shared.b16 {%0,%1,%2,%3}, [%4];"
                 : "=r"(r0), "=r"(r1), "=r"(r2), "=r"(r3) : "r"(addr));
}

__device__ __forceinline__ void mma_fp8(float* d, const uint32_t* a, uint32_t b0, uint32_t b1) {
    asm volatile(
        "mma.sync.aligned.m16n8k32.row.col.f32.e4m3.e4m3.f32 "
        "{%0,%1,%2,%3}, {%4,%5,%6,%7}, {%8,%9}, {%0,%1,%2,%3};"
        : "+f"(d[0]), "+f"(d[1]), "+f"(d[2]), "+f"(d[3])
        : "r"(a[0]), "r"(a[1]), "r"(a[2]), "r"(a[3]), "r"(b0), "r"(b1));
}

// ---------------- prep kernels ----------------
__global__ void init_amax_kernel() {
    g_amax_bits[0] = 0u;
    g_amax_bits[1] = 0u;
}

__global__ void amax_kernel(const float4* __restrict__ p, int n4, int slot) {
    float m = 0.0f;
    for (int i = blockIdx.x * blockDim.x + threadIdx.x; i < n4; i += gridDim.x * blockDim.x) {
        float4 v = p[i];
        m = fmaxf(m, fmaxf(fmaxf(fabsf(v.x), fabsf(v.y)), fmaxf(fabsf(v.z), fabsf(v.w))));
    }
    #pragma unroll
    for (int o = 16; o > 0; o >>= 1) m = fmaxf(m, __shfl_xor_sync(0xFFFFFFFFu, m, o));
    __shared__ float wm[8];
    if ((threadIdx.x & 31) == 0) wm[threadIdx.x >> 5] = m;
    __syncthreads();
    if (threadIdx.x < 8) {
        m = wm[threadIdx.x];
        #pragma unroll
        for (int o = 4; o > 0; o >>= 1) m = fmaxf(m, __shfl_xor_sync(0xFFu, m, o));
        if (threadIdx.x == 0) atomicMax(&g_amax_bits[slot], __float_as_uint(m));
    }
}

__device__ __forceinline__ unsigned char f2fp8(float v) {
    return (unsigned char)__nv_cvt_float_to_fp8(v, __NV_SATFINITE, __NV_E4M3);
}

__global__ void quant_x_kernel(const float4* __restrict__ x, int n4) {
    float s = 448.0f / fmaxf(__uint_as_float(g_amax_bits[0]), 1e-12f);
    uint32_t* q = reinterpret_cast<uint32_t*>(g_xq);
    for (int i = blockIdx.x * blockDim.x + threadIdx.x; i < n4; i += gridDim.x * blockDim.x) {
        float4 v = x[i];
        uint32_t b0 = f2fp8(v.x * s), b1 = f2fp8(v.y * s), b2 = f2fp8(v.z * s), b3 = f2fp8(v.w * s);
        q[i] = b0 | (b1 << 8) | (b2 << 16) | (b3 << 24);
    }
}

// quantize + transpose weight: w [K, OUT] (row-major) -> g_wq [OUT, K]
__global__ void quant_w_t_kernel(const float* __restrict__ w, int K, int OUT) {
    __shared__ unsigned char t[32][33];
    int o0 = blockIdx.x * 32, k0 = blockIdx.y * 32;
    int tx = threadIdx.x, ty = threadIdx.y;  // (32, 8)
    float s = 448.0f / fmaxf(__uint_as_float(g_amax_bits[1]), 1e-12f);
    #pragma unroll
    for (int i = 0; i < 4; i++) {
        int k = k0 + ty + 8 * i, o = o0 + tx;
        t[ty + 8 * i][tx] = f2fp8(w[(size_t)k * OUT + o] * s);
    }
    __syncthreads();
    #pragma unroll
    for (int i = 0; i < 4; i++) {
        int o = o0 + ty + 8 * i, k = k0 + tx;
        g_wq[(size_t)o * K + k] = t[tx][ty + 8 * i];
    }
}

// ---------------- GEMM kernel ----------------
// CTA tile 128(M) x 256(N), K-chunk 128B fp8, 3-stage cp.async pipeline.
// 8 warps: 2(m) x 4(n); each warp computes 64x64 with m16n8k32 fp8 mma.
#define STAGES      3
#define A_BYTES     16384                     // 128 rows x 128B
#define B_BYTES     32768                     // 256 rows x 128B
#define STAGE_BYTES (A_BYTES + B_BYTES)       // 48 KB
#define GEMM_SMEM_TOTAL (STAGES * STAGE_BYTES)  // 144 KB

__global__ void __launch_bounds__(256, 1)
gemm_fp8_kernel(float* __restrict__ out, const float* __restrict__ bias,
                int K, int NOUT, int tiles_n)
{
    extern __shared__ char smem[];
    uint32_t smem_base = smem_u32(smem);
    int tid = threadIdx.x;
    int wid = tid >> 5, lid = tid & 31;
    int wm = wid & 1, wn = wid >> 1;           // warp grid: 2m x 4n

    // rasterization: group 8 M-tiles
    int bid = blockIdx.x;
    int group = 8 * tiles_n;
    int g = bid / group, r = bid % group;
    int tm = g * 8 + (r % 8);
    int tn = r / 8;

    const unsigned char* Abase = g_xq + (size_t)tm * 128 * K;
    const unsigned char* Bbase = g_wq + (size_t)tn * 256 * K;

    // per-thread load slots: A 4 x 16B, B 8 x 16B per stage
    uint32_t aswz[4], bswz[8];
    int arow[4], brow[8], acol[4], bcol[8];
    #pragma unroll
    for (int i = 0; i < 4; i++) {
        int j = tid + 256 * i;                  // 0..1023
        arow[i] = j >> 3; acol[i] = (j & 7) << 4;
        aswz[i] = sw128((uint32_t)(arow[i] * 128 + acol[i]));
    }
    #pragma unroll
    for (int i = 0; i < 8; i++) {
        int j = tid + 256 * i;                  // 0..2047
        brow[i] = j >> 3; bcol[i] = (j & 7) << 4;
        bswz[i] = sw128((uint32_t)(brow[i] * 128 + bcol[i]));
    }

    auto issue_load = [&](int kc, int stg) {
        const unsigned char* ga = Abase + (size_t)kc * 128;
        const unsigned char* gb = Bbase + (size_t)kc * 128;
        uint32_t sa = smem_base + stg * STAGE_BYTES;
        uint32_t sb = sa + A_BYTES;
        #pragma unroll
        for (int i = 0; i < 4; i++)
            cp16(sa + aswz[i], ga + (size_t)arow[i] * K + acol[i]);
        #pragma unroll
        for (int i = 0; i < 8; i++)
            cp16(sb + bswz[i], gb + (size_t)brow[i] * K + bcol[i]);
    };

    float acc[4][8][4];
    #pragma unroll
    for (int mf = 0; mf < 4; mf++)
        #pragma unroll
        for (int j = 0; j < 8; j++)
            #pragma unroll
            for (int k = 0; k < 4; k++) acc[mf][j][k] = 0.0f;

    // ldmatrix lane addressing: row = lid%16, byte-half = (lid/16)*16
    int lr = lid & 15, lh = (lid >> 4) << 4;

    // double-buffered fragments
    uint32_t Ar[2][4][4], Br[2][4][4];

    const int kit = K / 128;
    issue_load(0, 0); CP_COMMIT();
    issue_load(1, 1); CP_COMMIT();

    for (int it = 0; it < kit; ++it) {
        CP_WAIT1();
        __syncthreads();        // all warps done reading stage (it-1)%3; stage it%3 ready
        if (it + 2 < kit) issue_load(it + 2, (it + 2) % STAGES);
        CP_COMMIT();

        int buf = it % STAGES;
        uint32_t sa = smem_base + buf * STAGE_BYTES;
        uint32_t sb = sa + A_BYTES;

        // prefetch step 0 fragments
        #pragma unroll
        for (int mf = 0; mf < 4; mf++) {
            uint32_t off = (uint32_t)((wm * 64 + mf * 16 + lr) * 128 + lh);
            ldm_x4(sa + sw128(off), Ar[0][mf][0], Ar[0][mf][1], Ar[0][mf][2], Ar[0][mf][3]);
        }
        #pragma unroll
        for (int nb = 0; nb < 4; nb++) {
            uint32_t off = (uint32_t)((wn * 64 + nb * 16 + lr) * 128 + lh);
            ldm_x4(sb + sw128(off), Br[0][nb][0], Br[0][nb][1], Br[0][nb][2], Br[0][nb][3]);
        }

        #pragma unroll
        for (int s = 0; s < 4; s++) {          // k32 steps within the 128B chunk
            int cb = s & 1, pb = cb ^ 1;
            if (s < 3) {                       // issue next step's LDSMs first
                #pragma unroll
                for (int mf = 0; mf < 4; mf++) {
                    uint32_t off = (uint32_t)((wm * 64 + mf * 16 + lr) * 128 + (s + 1) * 32 + lh);
                    ldm_x4(sa + sw128(off), Ar[pb][mf][0], Ar[pb][mf][1], Ar[pb][mf][2], Ar[pb][mf][3]);
                }
                #pragma unroll
                for (int nb = 0; nb < 4; nb++) {
                    uint32_t off = (uint32_t)((wn * 64 + nb * 16 + lr) * 128 + (s + 1) * 32 + lh);
                    ldm_x4(sb + sw128(off), Br[pb][nb][0], Br[pb][nb][1], Br[pb][nb][2], Br[pb][nb][3]);
                }
            }
            #pragma unroll
            for (int mf = 0; mf < 4; mf++)
                #pragma unroll
                for (int j = 0; j < 8; j++) {
                    uint32_t b0 = Br[cb][j >> 1][(j & 1) ? 1 : 0];
                    uint32_t b1 = Br[cb][j >> 1][(j & 1) ? 3 : 2];
                    mma_fp8(acc[mf][j], Ar[cb][mf], b0, b1);
                }
        }
    }

    // epilogue: scale + bias, float2 stores
    float ax = fmaxf(__uint_as_float(g_amax_bits[0]), 1e-12f);
    float aw = fmaxf(__uint_as_float(g_amax_bits[1]), 1e-12f);
    float inv = (ax / 448.0f) * (aw / 448.0f);
    int row0 = tm * 128 + wm * 64 + (lid >> 2);
    int col0 = tn * 256 + wn * 64 + (lid & 3) * 2;
    #pragma unroll
    for (int mf = 0; mf < 4; mf++) {
        #pragma unroll
        for (int j = 0; j < 8; j++) {
            int rr = row0 + mf * 16;
            int cc = col0 + j * 8;
            float2 bv = *reinterpret_cast<const float2*>(bias + cc);
            float2 v0, v1;
            v0.x = acc[mf][j][0] * inv + bv.x;
            v0.y = acc[mf][j][1] * inv + bv.y;
            v1.x = acc[mf][j][2] * inv + bv.x;
            v1.y = acc[mf][j][3] * inv + bv.y;
            *reinterpret_cast<float2*>(out + (size_t)rr * NOUT + cc) = v0;
            *reinterpret_cast<float2*>(out + (size_t)(rr + 8) * NOUT + cc) = v1;
        }
    }
}

// ---------------- host launcher ----------------
extern "C" void kernel_launch(void* const* d_in, const int* in_sizes, int n_in,
                              void* d_out, int out_size) {
    const float* x    = (const float*)d_in[0];
    const float* w    = (const float*)d_in[1];
    const float* bias = (const float*)d_in[2];
    float* out        = (float*)d_out;

    int OUT = in_sizes[2];
    int IN  = in_sizes[1] / OUT;
    int M   = in_sizes[0] / IN;
    // shapes: M=8192, IN=K=4096, OUT=4096 (static buffers sized for these)

    cudaFuncSetAttribute(gemm_fp8_kernel,
                         cudaFuncAttributeMaxDynamicSharedMemorySize, GEMM_SMEM_TOTAL);

    init_amax_kernel<<<1, 1>>>();
    amax_kernel<<<1024, 256>>>((const float4*)x, in_sizes[0] / 4, 0);
    amax_kernel<<<1024, 256>>>((const float4*)w, in_sizes[1] / 4, 1);
    quant_x_kernel<<<2048, 256>>>((const float4*)x, in_sizes[0] / 4);
    {
        dim3 grid(OUT / 32, IN / 32), block(32, 8);
        quant_w_t_kernel<<<grid, block>>>(w, IN, OUT);
    }
    {
        int tiles_m = M / 128, tiles_n = OUT / 256;
        gemm_fp8_kernel<<<tiles_m * tiles_n, 256, GEMM_SMEM_TOTAL>>>(
            out, bias, IN, OUT, tiles_n);
    }
}